// round 3
// baseline (speedup 1.0000x reference)
#include <cuda_runtime.h>

#define BSEG 4096
#define NMAX 500000
#define DS 128
#define VI 125
#define ROW_V 375      // 3*125
#define FEAT 503       // 128 + 375
#define MSTRIDE 512

// ---- device scratch (no allocations allowed) ----
__device__ int   g_cnt[BSEG];
__device__ int   g_off[BSEG];
__device__ int   g_pos[BSEG];
__device__ int   g_perm[NMAX];
__device__ float g_mean[BSEG * MSTRIDE];   // [b][0..127]=mean_s, [b][128..502]=mean_v flat (3*125)

// ---------------------------------------------------------------------------
__global__ void k_zero() {
    int t = blockIdx.x * blockDim.x + threadIdx.x;
    if (t < BSEG) g_cnt[t] = 0;
}

__global__ void k_count(const int* __restrict__ idx, int n) {
    int t = blockIdx.x * blockDim.x + threadIdx.x;
    if (t < n) atomicAdd(&g_cnt[idx[t]], 1);
}

// one block, 256 threads, 16 counts each -> exclusive scan of 4096 counts
__global__ void k_scan() {
    __shared__ int ssum[256];
    int t = threadIdx.x;
    int base = t * 16;
    int loc[16];
    int s = 0;
    #pragma unroll
    for (int j = 0; j < 16; j++) { loc[j] = g_cnt[base + j]; s += loc[j]; }
    ssum[t] = s;
    __syncthreads();
    // Hillis-Steele inclusive scan over 256 thread-sums
    for (int d = 1; d < 256; d <<= 1) {
        int v = (t >= d) ? ssum[t - d] : 0;
        __syncthreads();
        ssum[t] += v;
        __syncthreads();
    }
    int run = ssum[t] - s;   // exclusive prefix for this thread's chunk
    #pragma unroll
    for (int j = 0; j < 16; j++) {
        g_off[base + j] = run;
        g_pos[base + j] = run;
        run += loc[j];
    }
}

__global__ void k_scatter(const int* __restrict__ idx, int n) {
    int t = blockIdx.x * blockDim.x + threadIdx.x;
    if (t < n) {
        int p = atomicAdd(&g_pos[idx[t]], 1);
        g_perm[p] = t;
    }
}

// one block per segment; thread t accumulates feature t over the segment's nodes
__global__ void __launch_bounds__(512) k_reduce(const float* __restrict__ xs,
                                                const float* __restrict__ xv) {
    int b = blockIdx.x;
    int cnt = g_cnt[b];
    int off = g_off[b];
    int t = threadIdx.x;

    __shared__ int snid[256];

    const float* basep = (t < DS) ? (xs + t) : (xv + (t - DS));
    int stride = (t < DS) ? DS : ROW_V;

    float a0 = 0.f, a1 = 0.f, a2 = 0.f, a3 = 0.f;

    for (int cb = 0; cb < cnt; cb += 256) {
        int m = min(256, cnt - cb);
        __syncthreads();
        if (t < m) snid[t] = g_perm[off + cb + t];
        __syncthreads();
        if (t < FEAT) {
            int k = 0;
            for (; k + 4 <= m; k += 4) {
                a0 += __ldg(basep + snid[k]     * stride);
                a1 += __ldg(basep + snid[k + 1] * stride);
                a2 += __ldg(basep + snid[k + 2] * stride);
                a3 += __ldg(basep + snid[k + 3] * stride);
            }
            for (; k < m; k++) a0 += __ldg(basep + snid[k] * stride);
        }
    }
    if (t < FEAT) {
        float inv = 1.0f / (float)max(cnt, 1);
        g_mean[b * MSTRIDE + t] = (a0 + a1 + a2 + a3) * inv;
    }
}

// ---------------------------------------------------------------------------
__device__ __forceinline__ float sigmoidf(float x) {
    return 1.0f / (1.0f + expf(-x));
}

// one 128-thread block per segment: full GVP chain
__global__ void __launch_bounds__(128) k_gvp(
    const float* __restrict__ us,  const float* __restrict__ uv,
    const float* __restrict__ Wd,  const float* __restrict__ bd,
    const float* __restrict__ W1h, const float* __restrict__ W1vo,
    const float* __restrict__ W1so,const float* __restrict__ b1so,
    const float* __restrict__ W1g, const float* __restrict__ b1g,
    const float* __restrict__ W2h, const float* __restrict__ W2vo,
    const float* __restrict__ W2so,const float* __restrict__ b2so,
    const float* __restrict__ W2g, const float* __restrict__ b2g,
    float* __restrict__ out)
{
    int b = blockIdx.x;
    int t = threadIdx.x;

    __shared__ float sV[3][128];    // update_v
    __shared__ float sMs[128];      // mean_s
    __shared__ float sVh[3][128];
    __shared__ float sn1[160];      // [sh(128), update_s(32)]
    __shared__ float sS1[10];
    __shared__ float sV1[3][64];
    __shared__ float sVh2[3][64];
    __shared__ float sn2[74];       // [sh2(64), s1(10)]
    __shared__ float sS2[3];
    __shared__ float sVvo2[9];

    const float* mrow = g_mean + b * MSTRIDE;
    sMs[t] = mrow[t];
    #pragma unroll
    for (int r = 0; r < 3; r++)
        sV[r][t] = (t < VI) ? mrow[DS + r * VI + t]
                            : __ldg(&uv[b * 9 + r * 3 + (t - VI)]);
    __syncthreads();

    // GVP1: Vh = V @ W1h ; sh = ||Vh|| over the 3-axis
    {
        float v0 = 0.f, v1 = 0.f, v2 = 0.f;
        #pragma unroll 4
        for (int c = 0; c < 128; c++) {
            float w = __ldg(&W1h[c * 128 + t]);
            v0 += sV[0][c] * w; v1 += sV[1][c] * w; v2 += sV[2][c] * w;
        }
        sVh[0][t] = v0; sVh[1][t] = v1; sVh[2][t] = v2;
        sn1[t] = sqrtf(v0 * v0 + v1 * v1 + v2 * v2);
    }
    // update_s = [mean_s @ Wd + bd, u_s]
    if (t < 16) {
        float a = __ldg(&bd[t]);
        #pragma unroll 4
        for (int c = 0; c < 128; c++) a += sMs[c] * __ldg(&Wd[c * 16 + t]);
        sn1[128 + t] = a;
    } else if (t < 32) {
        sn1[128 + t] = __ldg(&us[b * 16 + (t - 16)]);
    }
    __syncthreads();

    // Vvo = Vh @ W1vo (threads 0..63); s1 = relu(sn1 @ W1so + b) (threads 64..73)
    float vv0 = 0.f, vv1 = 0.f, vv2 = 0.f;
    if (t < 64) {
        #pragma unroll 4
        for (int c = 0; c < 128; c++) {
            float w = __ldg(&W1vo[c * 64 + t]);
            vv0 += sVh[0][c] * w; vv1 += sVh[1][c] * w; vv2 += sVh[2][c] * w;
        }
    } else if (t < 74) {
        int j = t - 64;
        float a = __ldg(&b1so[j]);
        for (int c = 0; c < 160; c++) a += sn1[c] * __ldg(&W1so[c * 10 + j]);
        sS1[j] = fmaxf(a, 0.0f);
    }
    __syncthreads();

    // gate1 = sigmoid(sigmoid(s1) @ W1g + b1g); V1 = Vvo * gate1
    if (t < 64) {
        float g = __ldg(&b1g[t]);
        #pragma unroll
        for (int j = 0; j < 10; j++)
            g += sigmoidf(sS1[j]) * __ldg(&W1g[j * 64 + t]);
        float gate = sigmoidf(g);
        sV1[0][t] = vv0 * gate; sV1[1][t] = vv1 * gate; sV1[2][t] = vv2 * gate;
    }
    __syncthreads();

    // GVP2: Vh2 = V1 @ W2h; sh2 = norm; sn2 = [sh2, s1]
    if (t < 64) {
        float v0 = 0.f, v1 = 0.f, v2 = 0.f;
        #pragma unroll 4
        for (int c = 0; c < 64; c++) {
            float w = __ldg(&W2h[c * 64 + t]);
            v0 += sV1[0][c] * w; v1 += sV1[1][c] * w; v2 += sV1[2][c] * w;
        }
        sVh2[0][t] = v0; sVh2[1][t] = v1; sVh2[2][t] = v2;
        sn2[t] = sqrtf(v0 * v0 + v1 * v1 + v2 * v2);
    } else if (t < 74) {
        sn2[t] = sS1[t - 64];
    }
    __syncthreads();

    // Vvo2 (threads 0..8); s2 (threads 9..11)
    if (t < 9) {
        int r = t / 3, o = t % 3;
        float a = 0.f;
        #pragma unroll 4
        for (int h = 0; h < 64; h++) a += sVh2[r][h] * __ldg(&W2vo[h * 3 + o]);
        sVvo2[t] = a;
    } else if (t < 12) {
        int j = t - 9;
        float a = __ldg(&b2so[j]);
        for (int c = 0; c < 74; c++) a += sn2[c] * __ldg(&W2so[c * 3 + j]);
        sS2[j] = fmaxf(a, 0.0f);
    }
    __syncthreads();

    // gate2, final outputs: out = [s2 (B*3) | V2 (B*9)]
    if (t < 3) {
        float g = __ldg(&b2g[t]);
        #pragma unroll
        for (int j = 0; j < 3; j++)
            g += sigmoidf(sS2[j]) * __ldg(&W2g[j * 3 + t]);
        float gate = sigmoidf(g);
        out[b * 3 + t] = sS2[t];
        #pragma unroll
        for (int r = 0; r < 3; r++)
            out[BSEG * 3 + b * 9 + r * 3 + t] = sVvo2[r * 3 + t] * gate;
    }
}

// ---------------------------------------------------------------------------
extern "C" void kernel_launch(void* const* d_in, const int* in_sizes, int n_in,
                              void* d_out, int out_size) {
    const float* x_s  = (const float*)d_in[0];
    const float* x_v  = (const float*)d_in[1];
    const int*   idx  = (const int*)  d_in[2];
    const float* u_s  = (const float*)d_in[3];
    const float* u_v  = (const float*)d_in[4];
    const float* Wd   = (const float*)d_in[5];
    const float* bd   = (const float*)d_in[6];
    const float* W1h  = (const float*)d_in[7];
    const float* W1vo = (const float*)d_in[8];
    const float* W1so = (const float*)d_in[9];
    const float* b1so = (const float*)d_in[10];
    const float* W1g  = (const float*)d_in[11];
    const float* b1g  = (const float*)d_in[12];
    const float* W2h  = (const float*)d_in[13];
    const float* W2vo = (const float*)d_in[14];
    const float* W2so = (const float*)d_in[15];
    const float* b2so = (const float*)d_in[16];
    const float* W2g  = (const float*)d_in[17];
    const float* b2g  = (const float*)d_in[18];
    float* out = (float*)d_out;

    int n = in_sizes[2];   // number of nodes

    k_zero   <<<(BSEG + 255) / 256, 256>>>();
    k_count  <<<(n + 255) / 256, 256>>>(idx, n);
    k_scan   <<<1, 256>>>();
    k_scatter<<<(n + 255) / 256, 256>>>(idx, n);
    k_reduce <<<BSEG, 512>>>(x_s, x_v);
    k_gvp    <<<BSEG, 128>>>(u_s, u_v, Wd, bd, W1h, W1vo, W1so, b1so,
                             W1g, b1g, W2h, W2vo, W2so, b2so, W2g, b2g, out);
}